// round 1
// baseline (speedup 1.0000x reference)
#include <cuda_runtime.h>

// ---------------- problem constants (shapes fixed by the dataset) ----------
#define NMAX 100000
#define EMAX 1600000
#define NGRP 64

// ---------------- scratch (__device__ globals: no allocation allowed) ------
__device__ float g_kqv[NMAX * 16];   // per-node: k[0..4], q[5..9], v[10..14], pad
__device__ float g_agg1[NMAX * 5];   // conv1 accumulator, init = x@Ws1 + b1
__device__ float g_e2[EMAX];         // per-edge conv2 edge projection
__device__ float g_k2[NMAX];
__device__ float g_q2[NMAX];
__device__ float g_v2[NMAX];
__device__ float g_gsum[NGRP * 5];
__device__ float g_gsq[NGRP * 5];
__device__ float g_gcnt[NGRP];
__device__ float g_A[NGRP * 5];      // normed = A*x + B per (group, feature)
__device__ float g_B[NGRP * 5];

__device__ __forceinline__ float fast_sigmoid(float z) {
    return 1.0f / (1.0f + __expf(-z));
}

// ---------------------------------------------------------------------------
__global__ void zero_stats() {
    int t = threadIdx.x;
    if (t < NGRP * 5) { g_gsum[t] = 0.f; g_gsq[t] = 0.f; }
    if (t < NGRP) g_gcnt[t] = 0.f;
}

// ---------------------------------------------------------------------------
// Kernel A: node projections for conv1.
// Warp-per-node, grid-stride. W (256x20) lives in registers: lane l holds
// rows {l, l+32, ..., l+224} of the combined weight matrix (8*20 = 160 regs).
// Outputs h = 0..19 map to: k(Wk1) 0-4, q(Wq1) 5-9, v(Wv1) 10-14, skip(Ws1) 15-19.
__global__ __launch_bounds__(256, 1) void node_proj1(
    const float* __restrict__ x,
    const float* __restrict__ Wk, const float* __restrict__ bk,
    const float* __restrict__ Wq, const float* __restrict__ bq,
    const float* __restrict__ Wv, const float* __restrict__ bv,
    const float* __restrict__ Ws, const float* __restrict__ bs,
    int N)
{
    __shared__ float sW[256 * 20];
    int tid = threadIdx.x;
    for (int i = tid; i < 256 * 20; i += 256) {
        int c = i / 20, h = i % 20;
        float v;
        if (h < 5)       v = Wk[c * 5 + h];
        else if (h < 10) v = Wq[c * 5 + h - 5];
        else if (h < 15) v = Wv[c * 5 + h - 10];
        else             v = Ws[c * 5 + h - 15];
        sW[i] = v;
    }
    __syncthreads();

    int lane = tid & 31;
    int wid  = tid >> 5;

    float w[160];
#pragma unroll
    for (int j = 0; j < 8; j++)
#pragma unroll
        for (int h = 0; h < 20; h++)
            w[j * 20 + h] = sW[(j * 32 + lane) * 20 + h];

    // per-lane output slot and bias
    int sel;
    if (lane < 15) sel = lane;
    else if (lane >= 16 && lane < 21) sel = lane - 1;
    else sel = -1;

    float blane;
    if (lane < 5)                     blane = __ldg(&bk[lane]);
    else if (lane < 10)               blane = __ldg(&bq[lane - 5]);
    else if (lane < 15)               blane = __ldg(&bv[lane - 10]);
    else if (lane >= 16 && lane < 21) blane = __ldg(&bs[lane - 16]);
    else                              blane = 0.f;

    int warp    = blockIdx.x * 8 + wid;
    int wstride = gridDim.x * 8;

    for (int n = warp; n < N; n += wstride) {
        const float* xr = x + (size_t)n * 256 + lane;
        float acc[20];
#pragma unroll
        for (int h = 0; h < 20; h++) acc[h] = 0.f;

#pragma unroll
        for (int j = 0; j < 8; j++) {
            float xv = __ldg(xr + j * 32);
#pragma unroll
            for (int h = 0; h < 20; h++)
                acc[h] = fmaf(xv, w[j * 20 + h], acc[h]);
        }

#pragma unroll
        for (int h = 0; h < 20; h++) {
            acc[h] += __shfl_xor_sync(0xffffffffu, acc[h], 16);
            acc[h] += __shfl_xor_sync(0xffffffffu, acc[h], 8);
            acc[h] += __shfl_xor_sync(0xffffffffu, acc[h], 4);
            acc[h] += __shfl_xor_sync(0xffffffffu, acc[h], 2);
            acc[h] += __shfl_xor_sync(0xffffffffu, acc[h], 1);
        }

        float myval = 0.f;
#pragma unroll
        for (int h = 0; h < 20; h++)
            if (sel == h) myval = acc[h];
        myval += blane;

        if (lane < 15)
            g_kqv[(size_t)n * 16 + lane] = myval;
        else if (lane >= 16 && lane < 21)
            g_agg1[(size_t)n * 5 + (lane - 16)] = myval;
    }
}

// ---------------------------------------------------------------------------
// Kernel B: fused edge pass for conv1 + precompute of e2 for conv2.
// 8 lanes per edge; lane s holds We rows 4s..4s+3 in registers (24 values).
// eatt is loaded as one coalesced float4 per lane (512B/warp).
// After a 3-step group shuffle reduce, lanes 0..4 each own feature h=s:
// gather k[dst], q[src], v[src] (L2-resident), compute gate, atomicAdd msg.
__global__ __launch_bounds__(256) void edge_pass1(
    const float* __restrict__ eatt, const int* __restrict__ ei,
    const float* __restrict__ We1, const float* __restrict__ be1,
    const float* __restrict__ We2, const float* __restrict__ be2,
    int E)
{
    int tid = threadIdx.x;
    int s   = tid & 7;
    unsigned gmask = 0xFFu << (((tid >> 3) & 3) * 8);

    float we[24];
#pragma unroll
    for (int i = 0; i < 4; i++) {
        int c = s * 4 + i;
#pragma unroll
        for (int h = 0; h < 5; h++) we[i * 6 + h] = __ldg(&We1[c * 5 + h]);
        we[i * 6 + 5] = __ldg(&We2[c]);
    }
    float beh  = (s < 5) ? __ldg(&be1[s]) : 0.f;
    float be2v = __ldg(be2);

    const float4* ea4 = (const float4*)eatt;
    int gid     = blockIdx.x * 32 + (tid >> 3);
    int gstride = gridDim.x * 32;

    for (int e = gid; e < E; e += gstride) {
        int src = __ldg(&ei[e]);
        int dst = __ldg(&ei[E + e]);
        float4 ea = __ldg(&ea4[(size_t)e * 8 + s]);

        float p[6];
#pragma unroll
        for (int h = 0; h < 6; h++) {
            p[h] = ea.x * we[0 * 6 + h];
            p[h] = fmaf(ea.y, we[1 * 6 + h], p[h]);
            p[h] = fmaf(ea.z, we[2 * 6 + h], p[h]);
            p[h] = fmaf(ea.w, we[3 * 6 + h], p[h]);
        }
#pragma unroll
        for (int h = 0; h < 6; h++) {
            p[h] += __shfl_xor_sync(gmask, p[h], 4);
            p[h] += __shfl_xor_sync(gmask, p[h], 2);
            p[h] += __shfl_xor_sync(gmask, p[h], 1);
        }

        if (s == 5)
            g_e2[e] = p[5] + be2v;

        if (s < 5) {
            float eh = p[0];
            if (s == 1) eh = p[1];
            if (s == 2) eh = p[2];
            if (s == 3) eh = p[3];
            if (s == 4) eh = p[4];
            eh += beh;

            float k = __ldg(&g_kqv[(size_t)dst * 16 + s]);
            float q = __ldg(&g_kqv[(size_t)src * 16 + 5 + s]);
            float v = __ldg(&g_kqv[(size_t)src * 16 + 10 + s]);
            float gate = fast_sigmoid(k + q + 2.f * eh);
            atomicAdd(&g_agg1[(size_t)dst * 5 + s], gate * (v + eh));
        }
    }
}

// ---------------------------------------------------------------------------
// GraphNorm statistics. batch_idx is sorted, so most warps are group-uniform:
// warp-reduce then one lane of atomics. Boundary warps fall back to per-lane.
__global__ void gnorm_stats(const int* __restrict__ batch, int N)
{
    int n    = blockIdx.x * 256 + threadIdx.x;
    int lane = threadIdx.x & 31;
    bool valid = n < N;
    int g  = valid ? __ldg(&batch[n]) : 0;
    int g0 = __shfl_sync(0xffffffffu, g, 0);
    bool uni = __all_sync(0xffffffffu, valid && (g == g0));

    float v[5], sq[5];
#pragma unroll
    for (int h = 0; h < 5; h++) {
        v[h]  = valid ? g_agg1[(size_t)n * 5 + h] : 0.f;
        sq[h] = v[h] * v[h];
    }

    if (uni) {
#pragma unroll
        for (int h = 0; h < 5; h++) {
#pragma unroll
            for (int off = 16; off > 0; off >>= 1) {
                v[h]  += __shfl_xor_sync(0xffffffffu, v[h], off);
                sq[h] += __shfl_xor_sync(0xffffffffu, sq[h], off);
            }
        }
        if (lane == 0) {
#pragma unroll
            for (int h = 0; h < 5; h++) {
                atomicAdd(&g_gsum[g0 * 5 + h], v[h]);
                atomicAdd(&g_gsq[g0 * 5 + h], sq[h]);
            }
            atomicAdd(&g_gcnt[g0], 32.f);
        }
    } else if (valid) {
#pragma unroll
        for (int h = 0; h < 5; h++) {
            atomicAdd(&g_gsum[g * 5 + h], v[h]);
            atomicAdd(&g_gsq[g * 5 + h], sq[h]);
        }
        atomicAdd(&g_gcnt[g], 1.f);
    }
}

// normed = gw*(x - mean*ms)*inv_std + gb  ==  A*x + B
__global__ void gnorm_finalize(const float* __restrict__ gw,
                               const float* __restrict__ gb,
                               const float* __restrict__ gms)
{
    int t = threadIdx.x;
    if (t >= NGRP * 5) return;
    int g = t / 5, h = t % 5;
    float cnt  = fmaxf(g_gcnt[g], 1.f);
    float mean = g_gsum[t] / cnt;
    float ex2  = g_gsq[t] / cnt;
    float ms   = __ldg(&gms[h]);
    float d    = mean * ms;
    float var  = ex2 - 2.f * d * mean + d * d;   // E[(x - mean*ms)^2]
    float inv  = rsqrtf(var + 1e-5f);
    float wv   = __ldg(&gw[h]);
    g_A[t] = wv * inv;
    g_B[t] = __ldg(&gb[h]) - wv * inv * d;
}

// ---------------------------------------------------------------------------
// Apply norm + ReLU, then conv2 node projections (H1=5 -> H2=1 dots).
// out[] is seeded with the conv2 skip term (h@Ws2 + b2).
__global__ void node_proj2(
    const int* __restrict__ batch,
    const float* __restrict__ Wk2, const float* __restrict__ bk2,
    const float* __restrict__ Wq2, const float* __restrict__ bq2,
    const float* __restrict__ Wv2, const float* __restrict__ bv2,
    const float* __restrict__ Ws2, const float* __restrict__ b2,
    float* __restrict__ out, int N)
{
    int n = blockIdx.x * 256 + threadIdx.x;
    if (n >= N) return;
    int g = __ldg(&batch[n]);
    float k2 = __ldg(bk2), q2 = __ldg(bq2), v2 = __ldg(bv2), s2 = __ldg(b2);
#pragma unroll
    for (int h = 0; h < 5; h++) {
        float a  = g_A[g * 5 + h];
        float b  = g_B[g * 5 + h];
        float hv = fmaxf(fmaf(a, g_agg1[(size_t)n * 5 + h], b), 0.f);
        k2 = fmaf(hv, __ldg(&Wk2[h]), k2);
        q2 = fmaf(hv, __ldg(&Wq2[h]), q2);
        v2 = fmaf(hv, __ldg(&Wv2[h]), v2);
        s2 = fmaf(hv, __ldg(&Ws2[h]), s2);
    }
    g_k2[n] = k2;
    g_q2[n] = q2;
    g_v2[n] = v2;
    out[n]  = s2;
}

// ---------------------------------------------------------------------------
__global__ void edge_pass2(const int* __restrict__ ei,
                           float* __restrict__ out, int E)
{
    int e = blockIdx.x * 256 + threadIdx.x;
    if (e >= E) return;
    int src = __ldg(&ei[e]);
    int dst = __ldg(&ei[E + e]);
    float ev   = g_e2[e];
    float gate = fast_sigmoid(g_k2[dst] + g_q2[src] + 2.f * ev);
    atomicAdd(&out[dst], gate * (g_v2[src] + ev));
}

__global__ void final_sig(float* __restrict__ out, int N)
{
    int n = blockIdx.x * 256 + threadIdx.x;
    if (n < N) out[n] = fast_sigmoid(out[n]);
}

// ---------------------------------------------------------------------------
extern "C" void kernel_launch(void* const* d_in, const int* in_sizes, int n_in,
                              void* d_out, int out_size)
{
    const float* x     = (const float*)d_in[0];
    const float* eatt  = (const float*)d_in[1];
    const int*   ei    = (const int*)d_in[2];
    const int*   batch = (const int*)d_in[3];
    const float* Wk1 = (const float*)d_in[4];
    const float* bk1 = (const float*)d_in[5];
    const float* Wq1 = (const float*)d_in[6];
    const float* bq1 = (const float*)d_in[7];
    const float* Wv1 = (const float*)d_in[8];
    const float* bv1 = (const float*)d_in[9];
    const float* We1 = (const float*)d_in[10];
    const float* be1 = (const float*)d_in[11];
    const float* Ws1 = (const float*)d_in[12];
    const float* b1  = (const float*)d_in[13];
    const float* gw  = (const float*)d_in[14];
    const float* gb  = (const float*)d_in[15];
    const float* gms = (const float*)d_in[16];
    const float* Wk2 = (const float*)d_in[17];
    const float* bk2 = (const float*)d_in[18];
    const float* Wq2 = (const float*)d_in[19];
    const float* bq2 = (const float*)d_in[20];
    const float* Wv2 = (const float*)d_in[21];
    const float* bv2 = (const float*)d_in[22];
    const float* We2 = (const float*)d_in[23];
    const float* be2 = (const float*)d_in[24];
    const float* Ws2 = (const float*)d_in[25];
    const float* b2  = (const float*)d_in[26];
    float* out = (float*)d_out;

    int N = in_sizes[3];
    int E = in_sizes[2] / 2;
    if (N > NMAX) N = NMAX;
    if (E > EMAX) E = EMAX;

    int nb = (N + 255) / 256;
    int eb = (E + 255) / 256;

    zero_stats<<<1, 512>>>();
    node_proj1<<<592, 256>>>(x, Wk1, bk1, Wq1, bq1, Wv1, bv1, Ws1, b1, N);
    edge_pass1<<<2368, 256>>>(eatt, ei, We1, be1, We2, be2, E);
    gnorm_stats<<<nb, 256>>>(batch, N);
    gnorm_finalize<<<1, 512>>>(gw, gb, gms);
    node_proj2<<<nb, 256>>>(batch, Wk2, bk2, Wq2, bq2, Wv2, bv2, Ws2, b2, out, N);
    edge_pass2<<<eb, 256>>>(ei, out, E);
    final_sig<<<nb, 256>>>(out, N);
}

// round 3
// speedup vs baseline: 1.1653x; 1.1653x over previous
#include <cuda_runtime.h>

// ---------------- problem constants (shapes fixed by the dataset) ----------
#define NMAX 100000
#define EMAX 1600000
#define NGRP 64

// ---------------- scratch (__device__ globals: no allocation allowed) ------
__device__ float  g_kqv[NMAX * 16];   // per-node: k[0..4], q[5..9], v[10..14], pad
__device__ float  g_agg1[NMAX * 5];   // conv1 accumulator, seeded = x@Ws1 + b1
__device__ float  g_e2[EMAX];         // per-edge conv2 edge projection
__device__ float4 g_kqv2[NMAX];       // conv2 node proj: (k2, q2, v2, _)
__device__ float  g_gsum[NGRP * 5];
__device__ float  g_gsq[NGRP * 5];
__device__ float  g_gcnt[NGRP];
__device__ float  g_A[NGRP * 5];      // normed = A*x + B per (group, feature)
__device__ float  g_B[NGRP * 5];

__device__ __forceinline__ float fast_sigmoid(float z) {
    return 1.0f / (1.0f + __expf(-z));
}

// ---- packed f32x2 helpers (ptxas won't emit FFMA2 from C++) ---------------
__device__ __forceinline__ unsigned long long pack2(float a, float b) {
    unsigned long long r;
    asm("mov.b64 %0, {%1, %2};" : "=l"(r) : "f"(a), "f"(b));
    return r;
}
__device__ __forceinline__ void unpack2(unsigned long long v, float& a, float& b) {
    asm("mov.b64 {%0, %1}, %2;" : "=f"(a), "=f"(b) : "l"(v));
}
__device__ __forceinline__ void fma2(unsigned long long& d,
                                     unsigned long long a, unsigned long long b) {
    asm("fma.rn.f32x2 %0, %1, %2, %0;" : "+l"(d) : "l"(a), "l"(b));
}

// ---------------------------------------------------------------------------
__global__ void zero_stats() {
    int t = threadIdx.x;
    if (t < NGRP * 5) { g_gsum[t] = 0.f; g_gsq[t] = 0.f; }
    if (t < NGRP) g_gcnt[t] = 0.f;
}

// ---------------------------------------------------------------------------
// Kernel A: node projections for conv1 (a [N,256]x[256,20] GEMM).
// Warp-per-node. Lane l owns x columns c = l*8 .. l*8+7, with the matching
// 8x20 weight slice held in registers as 80 f32x2 pairs. Inner product uses
// fma.rn.f32x2 (80 packed FMAs/node instead of 160). Cross-lane reduction is
// a shared-memory transpose (5x STS.128, then 20 lanes sum 32 partials each)
// instead of a 200-instruction butterfly. x row loads are double-buffered.
__global__ __launch_bounds__(256) void node_proj1(
    const float* __restrict__ x,
    const float* __restrict__ Wk, const float* __restrict__ bk,
    const float* __restrict__ Wq, const float* __restrict__ bq,
    const float* __restrict__ Wv, const float* __restrict__ bv,
    const float* __restrict__ Ws, const float* __restrict__ bs,
    int N)
{
    __shared__ float sW[256 * 20];          // combined weights [c][h]
    __shared__ float sred[8 * 32 * 20];     // per-warp transpose buffer

    int tid  = threadIdx.x;
    int lane = tid & 31;
    int wid  = tid >> 5;

    for (int i = tid; i < 256 * 20; i += 256) {
        int c = i / 20, h = i % 20;
        float v;
        if (h < 5)       v = Wk[c * 5 + h];
        else if (h < 10) v = Wq[c * 5 + h - 5];
        else if (h < 15) v = Wv[c * 5 + h - 10];
        else             v = Ws[c * 5 + h - 15];
        sW[i] = v;
    }
    __syncthreads();

    // lane-private weight slice: 8 columns x 10 h-pairs
    unsigned long long w2[80];
#pragma unroll
    for (int i = 0; i < 8; i++) {
        int c = lane * 8 + i;
#pragma unroll
        for (int p = 0; p < 10; p++)
            w2[i * 10 + p] = pack2(sW[c * 20 + 2 * p], sW[c * 20 + 2 * p + 1]);
    }

    // per-lane bias (lane == output feature h for lanes 0..19)
    float blane = 0.f;
    if (lane < 5)       blane = __ldg(&bk[lane]);
    else if (lane < 10) blane = __ldg(&bq[lane - 5]);
    else if (lane < 15) blane = __ldg(&bv[lane - 10]);
    else if (lane < 20) blane = __ldg(&bs[lane - 15]);

    float* myred = &sred[wid * 640];

    int warp    = blockIdx.x * 8 + wid;
    int wstride = gridDim.x * 8;

    int n = warp;
    float4 a0, a1;
    if (n < N) {
        const float4* xr = (const float4*)(x + (size_t)n * 256 + lane * 8);
        a0 = __ldg(xr); a1 = __ldg(xr + 1);
    }

    while (n < N) {
        float4 c0 = a0, c1 = a1;
        int nn = n + wstride;
        if (nn < N) {                        // prefetch next row
            const float4* xr = (const float4*)(x + (size_t)nn * 256 + lane * 8);
            a0 = __ldg(xr); a1 = __ldg(xr + 1);
        }

        unsigned long long acc2[10];
#pragma unroll
        for (int p = 0; p < 10; p++) acc2[p] = 0ull;

        float xv[8] = {c0.x, c0.y, c0.z, c0.w, c1.x, c1.y, c1.z, c1.w};
#pragma unroll
        for (int i = 0; i < 8; i++) {
            unsigned long long xv2 = pack2(xv[i], xv[i]);
#pragma unroll
            for (int p = 0; p < 10; p++)
                fma2(acc2[p], xv2, w2[i * 10 + p]);
        }

        // transpose partials via smem: lane writes its 20 partials (5 float4)
        float accf[20];
#pragma unroll
        for (int p = 0; p < 10; p++) unpack2(acc2[p], accf[2 * p], accf[2 * p + 1]);
        float4* dst4 = (float4*)(myred + lane * 20);
#pragma unroll
        for (int q = 0; q < 5; q++)
            dst4[q] = make_float4(accf[4 * q], accf[4 * q + 1],
                                  accf[4 * q + 2], accf[4 * q + 3]);
        __syncwarp();

        if (lane < 20) {
            float s0 = 0.f, s1 = 0.f, s2 = 0.f, s3 = 0.f;
#pragma unroll
            for (int l = 0; l < 32; l += 4) {
                s0 += myred[(l + 0) * 20 + lane];
                s1 += myred[(l + 1) * 20 + lane];
                s2 += myred[(l + 2) * 20 + lane];
                s3 += myred[(l + 3) * 20 + lane];
            }
            float val = (s0 + s1) + (s2 + s3) + blane;
            if (lane < 15) g_kqv[(size_t)n * 16 + lane] = val;
            else           g_agg1[(size_t)n * 5 + (lane - 15)] = val;
        }
        __syncwarp();
        n = nn;
    }
}

// ---------------------------------------------------------------------------
// Kernel B: fused edge pass for conv1 + precompute of e2 for conv2.
// 8 lanes per edge; lane s holds We rows 4s..4s+3 in registers.
// eatt is loaded as one coalesced float4 per lane (512B/warp).
__global__ __launch_bounds__(256) void edge_pass1(
    const float* __restrict__ eatt, const int* __restrict__ ei,
    const float* __restrict__ We1, const float* __restrict__ be1,
    const float* __restrict__ We2, const float* __restrict__ be2,
    int E)
{
    int tid = threadIdx.x;
    int s   = tid & 7;
    unsigned gmask = 0xFFu << (((tid >> 3) & 3) * 8);

    float we[24];
#pragma unroll
    for (int i = 0; i < 4; i++) {
        int c = s * 4 + i;
#pragma unroll
        for (int h = 0; h < 5; h++) we[i * 6 + h] = __ldg(&We1[c * 5 + h]);
        we[i * 6 + 5] = __ldg(&We2[c]);
    }
    float beh  = (s < 5) ? __ldg(&be1[s]) : 0.f;
    float be2v = __ldg(be2);

    const float4* ea4 = (const float4*)eatt;
    int gid     = blockIdx.x * 32 + (tid >> 3);
    int gstride = gridDim.x * 32;

    for (int e = gid; e < E; e += gstride) {
        int src = __ldg(&ei[e]);
        int dst = __ldg(&ei[E + e]);
        float4 ea = __ldg(&ea4[(size_t)e * 8 + s]);

        float p[6];
#pragma unroll
        for (int h = 0; h < 6; h++) {
            p[h] = ea.x * we[0 * 6 + h];
            p[h] = fmaf(ea.y, we[1 * 6 + h], p[h]);
            p[h] = fmaf(ea.z, we[2 * 6 + h], p[h]);
            p[h] = fmaf(ea.w, we[3 * 6 + h], p[h]);
        }
#pragma unroll
        for (int h = 0; h < 6; h++) {
            p[h] += __shfl_xor_sync(gmask, p[h], 4);
            p[h] += __shfl_xor_sync(gmask, p[h], 2);
            p[h] += __shfl_xor_sync(gmask, p[h], 1);
        }

        if (s == 5)
            g_e2[e] = p[5] + be2v;

        if (s < 5) {
            float eh = p[0];
            if (s == 1) eh = p[1];
            if (s == 2) eh = p[2];
            if (s == 3) eh = p[3];
            if (s == 4) eh = p[4];
            eh += beh;

            float k = __ldg(&g_kqv[(size_t)dst * 16 + s]);
            float q = __ldg(&g_kqv[(size_t)src * 16 + 5 + s]);
            float v = __ldg(&g_kqv[(size_t)src * 16 + 10 + s]);
            float gate = fast_sigmoid(k + q + 2.f * eh);
            atomicAdd(&g_agg1[(size_t)dst * 5 + s], gate * (v + eh));
        }
    }
}

// ---------------------------------------------------------------------------
// GraphNorm statistics. One element per thread (grid covers N exactly — no
// grid-stride, so warp-collective ops never see divergent loop exits).
// Block-local smem accumulation; one global atomic per slot per block.
__global__ __launch_bounds__(256) void gnorm_stats(const int* __restrict__ batch, int N)
{
    __shared__ float ssum[NGRP * 5], ssq[NGRP * 5], scnt[NGRP];
    int tid  = threadIdx.x;
    int lane = tid & 31;
    for (int i = tid; i < NGRP * 5; i += 256) { ssum[i] = 0.f; ssq[i] = 0.f; }
    if (tid < NGRP) scnt[tid] = 0.f;
    __syncthreads();

    int n = blockIdx.x * 256 + tid;
    bool valid = n < N;
    int g  = valid ? __ldg(&batch[n]) : 0;
    int g0 = __shfl_sync(0xffffffffu, g, 0);
    bool uni = __all_sync(0xffffffffu, valid && (g == g0));

    float v[5], sq[5];
#pragma unroll
    for (int h = 0; h < 5; h++) {
        v[h]  = valid ? g_agg1[(size_t)n * 5 + h] : 0.f;
        sq[h] = v[h] * v[h];
    }

    if (uni) {
#pragma unroll
        for (int h = 0; h < 5; h++) {
#pragma unroll
            for (int off = 16; off > 0; off >>= 1) {
                v[h]  += __shfl_xor_sync(0xffffffffu, v[h], off);
                sq[h] += __shfl_xor_sync(0xffffffffu, sq[h], off);
            }
        }
        if (lane == 0) {
#pragma unroll
            for (int h = 0; h < 5; h++) {
                atomicAdd(&ssum[g0 * 5 + h], v[h]);
                atomicAdd(&ssq[g0 * 5 + h], sq[h]);
            }
            atomicAdd(&scnt[g0], 32.f);
        }
    } else if (valid) {
#pragma unroll
        for (int h = 0; h < 5; h++) {
            atomicAdd(&ssum[g * 5 + h], v[h]);
            atomicAdd(&ssq[g * 5 + h], sq[h]);
        }
        atomicAdd(&scnt[g], 1.f);
    }

    __syncthreads();
    for (int i = tid; i < NGRP * 5; i += 256) {
        if (ssum[i] != 0.f) atomicAdd(&g_gsum[i], ssum[i]);
        if (ssq[i]  != 0.f) atomicAdd(&g_gsq[i],  ssq[i]);
    }
    if (tid < NGRP && scnt[tid] != 0.f) atomicAdd(&g_gcnt[tid], scnt[tid]);
}

// normed = gw*(x - mean*ms)*inv_std + gb  ==  A*x + B
__global__ void gnorm_finalize(const float* __restrict__ gw,
                               const float* __restrict__ gb,
                               const float* __restrict__ gms)
{
    int t = threadIdx.x;
    if (t >= NGRP * 5) return;
    int g = t / 5, h = t % 5;
    float cnt  = fmaxf(g_gcnt[g], 1.f);
    float mean = g_gsum[t] / cnt;
    float ex2  = g_gsq[t] / cnt;
    float ms   = __ldg(&gms[h]);
    float d    = mean * ms;
    float var  = ex2 - 2.f * d * mean + d * d;   // E[(x - mean*ms)^2]
    float inv  = rsqrtf(var + 1e-5f);
    float wv   = __ldg(&gw[h]);
    g_A[t] = wv * inv;
    g_B[t] = __ldg(&gb[h]) - wv * inv * d;
}

// ---------------------------------------------------------------------------
// Apply norm + ReLU, then conv2 node projections (H1=5 -> H2=1 dots).
// out[] is seeded with the conv2 skip term (h@Ws2 + b2); (k2,q2,v2) go into
// one float4 per node so edge_pass2 needs only 2 gathered sectors per edge.
__global__ void node_proj2(
    const int* __restrict__ batch,
    const float* __restrict__ Wk2, const float* __restrict__ bk2,
    const float* __restrict__ Wq2, const float* __restrict__ bq2,
    const float* __restrict__ Wv2, const float* __restrict__ bv2,
    const float* __restrict__ Ws2, const float* __restrict__ b2,
    float* __restrict__ out, int N)
{
    int n = blockIdx.x * 256 + threadIdx.x;
    if (n >= N) return;
    int g = __ldg(&batch[n]);
    float k2 = __ldg(bk2), q2 = __ldg(bq2), v2 = __ldg(bv2), s2 = __ldg(b2);
#pragma unroll
    for (int h = 0; h < 5; h++) {
        float a  = g_A[g * 5 + h];
        float b  = g_B[g * 5 + h];
        float hv = fmaxf(fmaf(a, g_agg1[(size_t)n * 5 + h], b), 0.f);
        k2 = fmaf(hv, __ldg(&Wk2[h]), k2);
        q2 = fmaf(hv, __ldg(&Wq2[h]), q2);
        v2 = fmaf(hv, __ldg(&Wv2[h]), v2);
        s2 = fmaf(hv, __ldg(&Ws2[h]), s2);
    }
    g_kqv2[n] = make_float4(k2, q2, v2, 0.f);
    out[n]    = s2;
}

// ---------------------------------------------------------------------------
__global__ void edge_pass2(const int* __restrict__ ei,
                           float* __restrict__ out, int E)
{
    int e = blockIdx.x * 256 + threadIdx.x;
    if (e >= E) return;
    int src = __ldg(&ei[e]);
    int dst = __ldg(&ei[E + e]);
    float ev = g_e2[e];
    float4 d4 = __ldg(&g_kqv2[dst]);
    float4 s4 = __ldg(&g_kqv2[src]);
    float gate = fast_sigmoid(d4.x + s4.y + 2.f * ev);
    atomicAdd(&out[dst], gate * (s4.z + ev));
}

__global__ void final_sig(float* __restrict__ out, int N)
{
    int n = blockIdx.x * 256 + threadIdx.x;
    if (n < N) out[n] = fast_sigmoid(out[n]);
}

// ---------------------------------------------------------------------------
extern "C" void kernel_launch(void* const* d_in, const int* in_sizes, int n_in,
                              void* d_out, int out_size)
{
    const float* x     = (const float*)d_in[0];
    const float* eatt  = (const float*)d_in[1];
    const int*   ei    = (const int*)d_in[2];
    const int*   batch = (const int*)d_in[3];
    const float* Wk1 = (const float*)d_in[4];
    const float* bk1 = (const float*)d_in[5];
    const float* Wq1 = (const float*)d_in[6];
    const float* bq1 = (const float*)d_in[7];
    const float* Wv1 = (const float*)d_in[8];
    const float* bv1 = (const float*)d_in[9];
    const float* We1 = (const float*)d_in[10];
    const float* be1 = (const float*)d_in[11];
    const float* Ws1 = (const float*)d_in[12];
    const float* b1  = (const float*)d_in[13];
    const float* gw  = (const float*)d_in[14];
    const float* gb  = (const float*)d_in[15];
    const float* gms = (const float*)d_in[16];
    const float* Wk2 = (const float*)d_in[17];
    const float* bk2 = (const float*)d_in[18];
    const float* Wq2 = (const float*)d_in[19];
    const float* bq2 = (const float*)d_in[20];
    const float* Wv2 = (const float*)d_in[21];
    const float* bv2 = (const float*)d_in[22];
    const float* We2 = (const float*)d_in[23];
    const float* be2 = (const float*)d_in[24];
    const float* Ws2 = (const float*)d_in[25];
    const float* b2  = (const float*)d_in[26];
    float* out = (float*)d_out;

    int N = in_sizes[3];
    int E = in_sizes[2] / 2;
    if (N > NMAX) N = NMAX;
    if (E > EMAX) E = EMAX;

    int nb = (N + 255) / 256;
    int eb = (E + 255) / 256;

    zero_stats<<<1, 512>>>();
    node_proj1<<<148, 256>>>(x, Wk1, bk1, Wq1, bq1, Wv1, bv1, Ws1, b1, N);
    edge_pass1<<<1184, 256>>>(eatt, ei, We1, be1, We2, be2, E);
    gnorm_stats<<<nb, 256>>>(batch, N);
    gnorm_finalize<<<1, 512>>>(gw, gb, gms);
    node_proj2<<<nb, 256>>>(batch, Wk2, bk2, Wq2, bq2, Wv2, bv2, Ws2, b2, out, N);
    edge_pass2<<<eb, 256>>>(ei, out, E);
    final_sig<<<nb, 256>>>(out, N);
}